// round 1
// baseline (speedup 1.0000x reference)
#include <cuda_runtime.h>
#include <math.h>

#define NN   50000
#define EE   300000
#define IN_F 128
#define HH   256      // H = HF*AH
#define RR   3
#define AHD  4
#define HF   64
#define RH   (RR*HH)  // 768

// ---------------- scratch (device globals; no allocation allowed) ----------
__device__ float    g_hw[(size_t)NN*RH];     // h @ wW[r] for all r   (153.6MB)
__device__ float    g_oacc[(size_t)NN*RH];   // aggregated messages   (153.6MB)
__device__ float    g_as[NN];
__device__ float    g_ad[NN];
__device__ float    g_p[NN*RR*AHD];
__device__ float    g_q[NN*RR*AHD];
__device__ float    g_sgn[RR*EE];
__device__ float    g_ex[(size_t)RR*EE*AHD]; // alpha, then exp(alpha-max)
__device__ unsigned g_m[NN*RR*AHD];          // ordered-uint encoded max
__device__ float    g_den[NN*RR*AHD];
__device__ float    g_us[IN_F];
__device__ float    g_ud[IN_F];
__device__ float    g_c[2];                  // c_s (incl fb), c_d

// ---------------- helpers --------------------------------------------------
__device__ __forceinline__ unsigned f2ord(float f) {
    unsigned u = __float_as_uint(f);
    return (u & 0x80000000u) ? ~u : (u | 0x80000000u);
}
__device__ __forceinline__ float ord2f(unsigned u) {
    return __uint_as_float((u & 0x80000000u) ? (u & 0x7fffffffu) : ~u);
}
__device__ __forceinline__ float lrelu(float x) { return x > 0.f ? x : 0.01f * x; }

// ---------------- prep: fold d_liner+f_liner into two 128-vectors ----------
__global__ void prep_kernel(const float* __restrict__ dW, const float* __restrict__ db,
                            const float* __restrict__ fW, const float* __restrict__ fb) {
    int k = threadIdx.x;
    if (k < IN_F) {
        float us = 0.f, ud = 0.f;
        for (int j = 0; j < HH; j++) {
            float w  = dW[k*HH + j];
            float f0 = fW[j], f1 = fW[HH + j], f2 = fW[2*HH + j];
            us += w * (f0 + f2);
            ud += w * (f1 - f2);
        }
        g_us[k] = us; g_ud[k] = ud;
    }
    if (k == 0) {
        float cs = 0.f, cd = 0.f;
        for (int j = 0; j < HH; j++) {
            float b  = db[j];
            float f0 = fW[j], f1 = fW[HH + j], f2 = fW[2*HH + j];
            cs += b * (f0 + f2);
            cd += b * (f1 - f2);
        }
        g_c[0] = cs + fb[0];
        g_c[1] = cd;
    }
}

// ---------------- per-node sign scalars: a_s, a_d --------------------------
__global__ void node_scalar_kernel(const float* __restrict__ h) {
    int warp = (blockIdx.x * blockDim.x + threadIdx.x) >> 5;
    int lane = threadIdx.x & 31;
    if (warp >= NN) return;
    float4 hv = *(const float4*)(h + (size_t)warp * IN_F + lane * 4);
    float4 us = *(const float4*)(g_us + lane * 4);
    float4 ud = *(const float4*)(g_ud + lane * 4);
    float ps = hv.x*us.x + hv.y*us.y + hv.z*us.z + hv.w*us.w;
    float pd = hv.x*ud.x + hv.y*ud.y + hv.z*ud.z + hv.w*ud.w;
    #pragma unroll
    for (int o = 16; o; o >>= 1) {
        ps += __shfl_xor_sync(0xffffffffu, ps, o);
        pd += __shfl_xor_sync(0xffffffffu, pd, o);
    }
    if (lane == 0) { g_as[warp] = ps + g_c[0]; g_ad[warp] = pd + g_c[1]; }
}

// ---------------- fp32 tiled GEMM with bias: C[M,128cols] = A@B + bias -----
// BM=BN=128, BK=8, 256 threads, 8x8 per thread, smem double buffered.
__global__ void __launch_bounds__(256) sgemm_bias_kernel(
    const float* __restrict__ A, int lda,
    const float* __restrict__ B, int ldb,
    const float* __restrict__ bias,
    float* __restrict__ C, int ldc,
    int M, int K)
{
    __shared__ float As[2][8][128];
    __shared__ float Bs[2][8][128];
    int tid  = threadIdx.x;
    int bm   = blockIdx.y * 128, bn = blockIdx.x * 128;
    int arow = tid >> 1,  acol = (tid & 1) << 2;
    int brow = tid >> 5,  bcol = (tid & 31) << 2;
    bool aok = (bm + arow) < M;
    const float* Ap = A + (size_t)(bm + arow) * lda + acol;
    const float* Bp = B + (size_t)brow * ldb + bn + bcol;

    float4 av = aok ? *(const float4*)Ap : make_float4(0.f,0.f,0.f,0.f);
    float4 bv = *(const float4*)Bp;
    As[0][acol+0][arow]=av.x; As[0][acol+1][arow]=av.y;
    As[0][acol+2][arow]=av.z; As[0][acol+3][arow]=av.w;
    *(float4*)&Bs[0][brow][bcol] = bv;
    __syncthreads();

    int tx = tid & 15, ty = tid >> 4;
    float acc[8][8];
    #pragma unroll
    for (int i = 0; i < 8; i++)
        #pragma unroll
        for (int j = 0; j < 8; j++) acc[i][j] = 0.f;

    int nt = K >> 3;
    for (int t = 0; t < nt; t++) {
        float4 av2, bv2;
        if (t + 1 < nt) {
            int ko = (t + 1) << 3;
            av2 = aok ? *(const float4*)(Ap + ko) : make_float4(0.f,0.f,0.f,0.f);
            bv2 = *(const float4*)(Bp + (size_t)ko * ldb);
        }
        int b = t & 1;
        #pragma unroll
        for (int k = 0; k < 8; k++) {
            float af[8], bf[8];
            *(float4*)&af[0] = *(const float4*)&As[b][k][ty*8];
            *(float4*)&af[4] = *(const float4*)&As[b][k][ty*8+4];
            *(float4*)&bf[0] = *(const float4*)&Bs[b][k][tx*8];
            *(float4*)&bf[4] = *(const float4*)&Bs[b][k][tx*8+4];
            #pragma unroll
            for (int i = 0; i < 8; i++)
                #pragma unroll
                for (int j = 0; j < 8; j++)
                    acc[i][j] = fmaf(af[i], bf[j], acc[i][j]);
        }
        if (t + 1 < nt) {
            int nb = b ^ 1;
            As[nb][acol+0][arow]=av2.x; As[nb][acol+1][arow]=av2.y;
            As[nb][acol+2][arow]=av2.z; As[nb][acol+3][arow]=av2.w;
            *(float4*)&Bs[nb][brow][bcol] = bv2;
            __syncthreads();
        }
    }

    #pragma unroll
    for (int i = 0; i < 8; i++) {
        int row = bm + ty*8 + i;
        if (row >= M) break;
        int col = bn + tx*8;
        float* cp = C + (size_t)row * ldc + col;
        float4 o0, o1;
        o0.x = acc[i][0] + bias[col+0]; o0.y = acc[i][1] + bias[col+1];
        o0.z = acc[i][2] + bias[col+2]; o0.w = acc[i][3] + bias[col+3];
        o1.x = acc[i][4] + bias[col+4]; o1.y = acc[i][5] + bias[col+5];
        o1.z = acc[i][6] + bias[col+6]; o1.w = acc[i][7] + bias[col+7];
        *(float4*)cp       = o0;
        *(float4*)(cp + 4) = o1;
    }
}

// ---------------- per-node per-head attention projections p, q -------------
__global__ void pq_kernel(const float* __restrict__ aW) {
    int gw   = (blockIdx.x * blockDim.x + threadIdx.x) >> 5;
    int lane = threadIdx.x & 31;
    if (gw >= NN * RR) return;
    int n = gw / RR, r = gw - n * RR;
    const float* row = g_hw + (size_t)n * RH + r * HH + lane * 8;
    float4 v0 = *(const float4*)row;
    float4 v1 = *(const float4*)(row + 4);
    int jo = (lane & 7) * 8;
    const float* ap = aW + r * 2 * HF + jo;
    const float* aq = aW + r * 2 * HF + HF + jo;
    float p = v0.x*ap[0]+v0.y*ap[1]+v0.z*ap[2]+v0.w*ap[3]
            + v1.x*ap[4]+v1.y*ap[5]+v1.z*ap[6]+v1.w*ap[7];
    float q = v0.x*aq[0]+v0.y*aq[1]+v0.z*aq[2]+v0.w*aq[3]
            + v1.x*aq[4]+v1.y*aq[5]+v1.z*aq[6]+v1.w*aq[7];
    #pragma unroll
    for (int o = 4; o; o >>= 1) {
        p += __shfl_xor_sync(0xffffffffu, p, o);
        q += __shfl_xor_sync(0xffffffffu, q, o);
    }
    if ((lane & 7) == 0) {
        int head = lane >> 3;
        g_p[(n*RR + r)*AHD + head] = p;
        g_q[(n*RR + r)*AHD + head] = q;
    }
}

// ---------------- edge phase 1: sign, alpha, segment max -------------------
__global__ void edge_alpha_kernel(const int* __restrict__ src, const int* __restrict__ dst,
                                  const float* __restrict__ ab) {
    int idx = blockIdx.x * blockDim.x + threadIdx.x;
    if (idx >= RR * EE) return;
    int r = idx / EE;
    int s = src[idx], d = dst[idx];
    float sc = g_as[s] + g_ad[d];
    float sg = (sc > 0.f) ? 1.f : ((sc < 0.f) ? -1.f : 0.f);
    float4 pv = *(const float4*)(g_p + (s*RR + r)*AHD);
    float4 qv = *(const float4*)(g_q + (d*RR + r)*AHD);
    float abr = ab[r];
    float4 al;
    al.x = lrelu(sg*pv.x + qv.x + abr);
    al.y = lrelu(sg*pv.y + qv.y + abr);
    al.z = lrelu(sg*pv.z + qv.z + abr);
    al.w = lrelu(sg*pv.w + qv.w + abr);
    *(float4*)(g_ex + (size_t)idx * AHD) = al;
    g_sgn[idx] = sg;
    unsigned* mb = g_m + (d*RR + r)*AHD;
    atomicMax(mb+0, f2ord(al.x));
    atomicMax(mb+1, f2ord(al.y));
    atomicMax(mb+2, f2ord(al.z));
    atomicMax(mb+3, f2ord(al.w));
}

// ---------------- edge phase 2: exp + segment sum --------------------------
__global__ void edge_exp_kernel(const int* __restrict__ dst) {
    int idx = blockIdx.x * blockDim.x + threadIdx.x;
    if (idx >= RR * EE) return;
    int r = idx / EE;
    int d = dst[idx];
    uint4  mu = *(const uint4*)(g_m + (d*RR + r)*AHD);
    float4 al = *(const float4*)(g_ex + (size_t)idx * AHD);
    float4 e;
    e.x = expf(al.x - ord2f(mu.x));
    e.y = expf(al.y - ord2f(mu.y));
    e.z = expf(al.z - ord2f(mu.z));
    e.w = expf(al.w - ord2f(mu.w));
    *(float4*)(g_ex + (size_t)idx * AHD) = e;
    float* dn = g_den + (d*RR + r)*AHD;
    atomicAdd(dn+0, e.x);
    atomicAdd(dn+1, e.y);
    atomicAdd(dn+2, e.z);
    atomicAdd(dn+3, e.w);
}

// ---------------- edge phase 3: weighted message scatter (heavy) -----------
__global__ void aggregate_kernel(const int* __restrict__ src, const int* __restrict__ dst) {
    int gw   = (blockIdx.x * blockDim.x + threadIdx.x) >> 5;
    int lane = threadIdx.x & 31;
    if (gw >= RR * EE) return;
    int r = gw / EE;
    int s = src[gw], d = dst[gw];
    float sg = g_sgn[gw];
    int head = lane >> 3;
    float w = g_ex[(size_t)gw * AHD + head] / g_den[(d*RR + r)*AHD + head];
    float coef = w * sg;
    const float4* hs = (const float4*)(g_hw   + (size_t)s * RH + r * HH) + lane * 2;
    float4*       od = (float4*)      (g_oacc + (size_t)d * RH + r * HH) + lane * 2;
    float4 v0 = hs[0], v1 = hs[1];
    atomicAdd(od,     make_float4(coef*v0.x, coef*v0.y, coef*v0.z, coef*v0.w));
    atomicAdd(od + 1, make_float4(coef*v1.x, coef*v1.y, coef*v1.z, coef*v1.w));
}

// ---------------- launch ---------------------------------------------------
extern "C" void kernel_launch(void* const* d_in, const int* in_sizes, int n_in,
                              void* d_out, int out_size) {
    const float* h    = (const float*)d_in[0];
    const float* dW   = (const float*)d_in[1];
    const float* db   = (const float*)d_in[2];
    const float* fW   = (const float*)d_in[3];
    const float* fb   = (const float*)d_in[4];
    const float* wW   = (const float*)d_in[5];
    const float* wb   = (const float*)d_in[6];
    const float* aW   = (const float*)d_in[7];
    const float* ab   = (const float*)d_in[8];
    const float* linW = (const float*)d_in[9];
    const float* linb = (const float*)d_in[10];
    const int*   src  = (const int*)d_in[11];
    const int*   dst  = (const int*)d_in[12];
    float* out = (float*)d_out;

    float *hw, *oacc, *den; unsigned* m;
    cudaGetSymbolAddress((void**)&hw,   g_hw);
    cudaGetSymbolAddress((void**)&oacc, g_oacc);
    cudaGetSymbolAddress((void**)&m,    g_m);
    cudaGetSymbolAddress((void**)&den,  g_den);

    cudaMemsetAsync(oacc, 0, (size_t)NN * RH * sizeof(float), 0);
    cudaMemsetAsync(m,    0, (size_t)NN * RR * AHD * sizeof(unsigned), 0);
    cudaMemsetAsync(den,  0, (size_t)NN * RR * AHD * sizeof(float), 0);

    prep_kernel<<<1, 128>>>(dW, db, fW, fb);
    node_scalar_kernel<<<(NN + 7) / 8, 256>>>(h);

    for (int r = 0; r < RR; r++) {
        sgemm_bias_kernel<<<dim3(HH / 128, (NN + 127) / 128), 256>>>(
            h, IN_F,
            wW + (size_t)r * IN_F * HH, HH,
            wb + r * HH,
            hw + r * HH, RH,
            NN, IN_F);
    }

    pq_kernel<<<(NN * RR + 7) / 8, 256>>>(aW);
    edge_alpha_kernel<<<(RR * EE + 255) / 256, 256>>>(src, dst, ab);
    edge_exp_kernel<<<(RR * EE + 255) / 256, 256>>>(dst);
    aggregate_kernel<<<(RR * EE + 7) / 8, 256>>>(src, dst);

    sgemm_bias_kernel<<<dim3(HH / 128, (NN + 127) / 128), 256>>>(
        oacc, RH, linW, HH, linb, out, HH, NN, RH);
}

// round 3
// speedup vs baseline: 1.0387x; 1.0387x over previous
#include <cuda_runtime.h>
#include <cuda_bf16.h>
#include <math.h>
#include <cstdint>

#define NN   50000
#define EE   300000
#define IN_F 128
#define HH   256      // H = HF*AH
#define RR   3
#define AHD  4
#define HF   64
#define RH   (RR*HH)  // 768

// ---------------- scratch (device globals; no allocation allowed) ----------
__device__ float g_hw[(size_t)NN*RH];     // h @ wW[r] for all r   (153.6MB)
__device__ float g_oacc[(size_t)NN*RH];   // aggregated messages   (153.6MB)
__device__ float g_as[NN];
__device__ float g_ad[NN];
__device__ float g_p[NN*RR*AHD];
__device__ float g_q[NN*RR*AHD];
__device__ float g_ex[(size_t)RR*EE*AHD]; // sign * exp(alpha)
__device__ float g_den[NN*RR*AHD];
__device__ float g_us[IN_F];
__device__ float g_ud[IN_F];
__device__ float g_c[2];                  // c_s (incl fb), c_d
__device__ float g_wpa[24*IN_F];          // folded p/q directions [r*8+head*2+pq][128]
__device__ float g_pqc[24];               // folded p/q constants (from wb)
__device__ float g_wWt[RR*HH*IN_F];       // wW transposed -> [r][n=256][k=128]
__device__ float g_linWt[HH*RH];          // linW transposed -> [n=256][k=768]

// ---------------- helpers --------------------------------------------------
__device__ __forceinline__ float lrelu(float x) { return x > 0.f ? x : 0.01f * x; }
__device__ __forceinline__ float dot4(float4 a, float4 b) {
    return a.x*b.x + a.y*b.y + a.z*b.z + a.w*b.w;
}

// ================= bf16 split mma.sync GEMM ================================
// C[M, 256] = A[M,K] @ B[K,256] + bias, A row-major (lda), Bt = B^T [256,K].
// CTA tile 128x128, K chunk 32, 8 warps (wm = wid&3 -> 32 rows, wn = wid>>2 -> 64 cols).
// 3-pass bf16 split: acc += Ahi*Bhi + Ahi*Blo + Alo*Bhi.

__device__ __forceinline__ void mma16816(float* c, const uint32_t* a, uint32_t b0, uint32_t b1) {
    asm volatile(
        "mma.sync.aligned.m16n8k16.row.col.f32.bf16.bf16.f32 "
        "{%0,%1,%2,%3}, {%4,%5,%6,%7}, {%8,%9}, {%0,%1,%2,%3};"
        : "+f"(c[0]), "+f"(c[1]), "+f"(c[2]), "+f"(c[3])
        : "r"(a[0]), "r"(a[1]), "r"(a[2]), "r"(a[3]), "r"(b0), "r"(b1));
}

__device__ __forceinline__ void cvt_store(char* hi_base, char* lo_base, int soff, float4 v) {
    __nv_bfloat162 h01 = __floats2bfloat162_rn(v.x, v.y);
    __nv_bfloat162 h23 = __floats2bfloat162_rn(v.z, v.w);
    float lx = v.x - __low2float(h01),  ly = v.y - __high2float(h01);
    float lz = v.z - __low2float(h23),  lw = v.w - __high2float(h23);
    __nv_bfloat162 l01 = __floats2bfloat162_rn(lx, ly);
    __nv_bfloat162 l23 = __floats2bfloat162_rn(lz, lw);
    uint2 hu, lu;
    hu.x = *(uint32_t*)&h01; hu.y = *(uint32_t*)&h23;
    lu.x = *(uint32_t*)&l01; lu.y = *(uint32_t*)&l23;
    *(uint2*)(hi_base + soff) = hu;
    *(uint2*)(lo_base + soff) = lu;
}

__global__ void __launch_bounds__(256) mma_gemm_kernel(
    const float* __restrict__ A, int lda,
    const float* __restrict__ Bt0, int ldb, int b_stride,
    const float* __restrict__ bias0, int bias_stride,
    float* __restrict__ C0, int ldc, int c_stride,
    int M, int K)
{
    __shared__ __align__(16) char sAh[8192];
    __shared__ __align__(16) char sAl[8192];
    __shared__ __align__(16) char sBh[8192];
    __shared__ __align__(16) char sBl[8192];

    const float* Bt   = Bt0   + (size_t)blockIdx.z * b_stride;
    const float* bias = bias0 + (size_t)blockIdx.z * bias_stride;
    float*       C    = C0    + (size_t)blockIdx.z * c_stride;

    int tid = threadIdx.x;
    int wid = tid >> 5, lane = tid & 31;
    int g = lane >> 2, tig = lane & 3;
    int wm = wid & 3, wn = wid >> 2;
    int bm = blockIdx.y * 128, bn = blockIdx.x * 128;

    float c[2][8][4];
    #pragma unroll
    for (int t = 0; t < 2; t++)
        #pragma unroll
        for (int nt = 0; nt < 8; nt++)
            #pragma unroll
            for (int i = 0; i < 4; i++) c[t][nt][i] = 0.f;

    int nch = K >> 5;
    float4 areg[4], breg[4];
    int rrow[4], rkq[4];

    // fetch chunk 0
    #pragma unroll
    for (int i = 0; i < 4; i++) {
        int lin = i * 256 + tid;
        int row = lin >> 3, kq = (lin & 7) << 2;
        rrow[i] = row; rkq[i] = kq;
        int gr = bm + row;
        areg[i] = (gr < M) ? *(const float4*)(A + (size_t)gr * lda + kq)
                           : make_float4(0.f, 0.f, 0.f, 0.f);
        breg[i] = *(const float4*)(Bt + (size_t)(bn + row) * ldb + kq);
    }
    #pragma unroll
    for (int i = 0; i < 4; i++) {
        int soff = rrow[i] * 64 + ((rkq[i] << 1) ^ ((rrow[i] & 7) << 3));
        cvt_store(sAh, sAl, soff, areg[i]);
        cvt_store(sBh, sBl, soff, breg[i]);
    }
    __syncthreads();

    for (int ch = 0; ch < nch; ch++) {
        bool more = (ch + 1) < nch;
        if (more) {
            int kc = (ch + 1) << 5;
            #pragma unroll
            for (int i = 0; i < 4; i++) {
                int gr = bm + rrow[i];
                areg[i] = (gr < M) ? *(const float4*)(A + (size_t)gr * lda + kc + rkq[i])
                                   : make_float4(0.f, 0.f, 0.f, 0.f);
                breg[i] = *(const float4*)(Bt + (size_t)(bn + rrow[i]) * ldb + kc + rkq[i]);
            }
        }
        // compute on current smem chunk
        #pragma unroll
        for (int ks = 0; ks < 2; ks++) {
            uint32_t ah[2][4], al[2][4];
            int kb = ks * 32 + tig * 4;
            #pragma unroll
            for (int t = 0; t < 2; t++) {
                int r = wm * 32 + t * 16 + g;
                int x = (r & 7) << 3;
                int o0 = r * 64 + (kb ^ x);
                int o2 = r * 64 + ((kb + 16) ^ x);
                ah[t][0] = *(uint32_t*)(sAh + o0);
                ah[t][1] = *(uint32_t*)(sAh + o0 + 512);
                ah[t][2] = *(uint32_t*)(sAh + o2);
                ah[t][3] = *(uint32_t*)(sAh + o2 + 512);
                al[t][0] = *(uint32_t*)(sAl + o0);
                al[t][1] = *(uint32_t*)(sAl + o0 + 512);
                al[t][2] = *(uint32_t*)(sAl + o2);
                al[t][3] = *(uint32_t*)(sAl + o2 + 512);
            }
            #pragma unroll
            for (int nt = 0; nt < 8; nt++) {
                int n = wn * 64 + nt * 8 + g;
                int x = (n & 7) << 3;
                int o0 = n * 64 + (kb ^ x);
                int o1 = n * 64 + ((kb + 16) ^ x);
                uint32_t bh0 = *(uint32_t*)(sBh + o0);
                uint32_t bh1 = *(uint32_t*)(sBh + o1);
                uint32_t bl0 = *(uint32_t*)(sBl + o0);
                uint32_t bl1 = *(uint32_t*)(sBl + o1);
                #pragma unroll
                for (int t = 0; t < 2; t++) {
                    mma16816(c[t][nt], ah[t], bh0, bh1);
                    mma16816(c[t][nt], ah[t], bl0, bl1);
                    mma16816(c[t][nt], al[t], bh0, bh1);
                }
            }
        }
        if (more) {
            __syncthreads();
            #pragma unroll
            for (int i = 0; i < 4; i++) {
                int soff = rrow[i] * 64 + ((rkq[i] << 1) ^ ((rrow[i] & 7) << 3));
                cvt_store(sAh, sAl, soff, areg[i]);
                cvt_store(sBh, sBl, soff, breg[i]);
            }
            __syncthreads();
        }
    }

    // epilogue
    #pragma unroll
    for (int t = 0; t < 2; t++) {
        int row0 = bm + wm * 32 + t * 16 + g;
        #pragma unroll
        for (int nt = 0; nt < 8; nt++) {
            int col = bn + wn * 64 + nt * 8 + tig * 2;
            float b0 = bias[col], b1 = bias[col + 1];
            if (row0 < M) {
                float2 o = make_float2(c[t][nt][0] + b0, c[t][nt][1] + b1);
                *(float2*)(C + (size_t)row0 * ldc + col) = o;
            }
            if (row0 + 8 < M) {
                float2 o = make_float2(c[t][nt][2] + b0, c[t][nt][3] + b1);
                *(float2*)(C + (size_t)(row0 + 8) * ldc + col) = o;
            }
        }
    }
}

// ---------------- weight transposes: wWt[r][n][k], linWt[n][k] -------------
__global__ void transpose_weights_kernel(const float* __restrict__ wW,
                                         const float* __restrict__ linW) {
    int idx = blockIdx.x * blockDim.x + threadIdx.x;
    if (idx < RR * HH * IN_F) {
        int r = idx / (HH * IN_F);
        int rem = idx - r * HH * IN_F;
        int n = rem / IN_F, k = rem - n * IN_F;
        g_wWt[idx] = wW[(size_t)r * IN_F * HH + (size_t)k * HH + n];
    }
    if (idx < HH * RH) {
        int n = idx / RH, k = idx - n * RH;
        g_linWt[idx] = linW[(size_t)k * HH + n];
    }
}

// ---------------- prep: fold d_liner+f_liner into two 128-vectors ----------
__global__ void prep_kernel(const float* __restrict__ dW, const float* __restrict__ db,
                            const float* __restrict__ fW, const float* __restrict__ fb) {
    int k = threadIdx.x;
    if (k < IN_F) {
        float us = 0.f, ud = 0.f;
        for (int j = 0; j < HH; j++) {
            float w  = dW[k*HH + j];
            float f0 = fW[j], f1 = fW[HH + j], f2 = fW[2*HH + j];
            us += w * (f0 + f2);
            ud += w * (f1 - f2);
        }
        g_us[k] = us; g_ud[k] = ud;
    }
    if (k == 0) {
        float cs = 0.f, cd = 0.f;
        for (int j = 0; j < HH; j++) {
            float b  = db[j];
            float f0 = fW[j], f1 = fW[HH + j], f2 = fW[2*HH + j];
            cs += b * (f0 + f2);
            cd += b * (f1 - f2);
        }
        g_c[0] = cs + fb[0];
        g_c[1] = cd;
    }
}

// ---------------- fold w_liner+attention into 24 p/q directions ------------
// wpa[v][k] with v = r*8 + head*2 + pq:  sum_i wW[r][k][head*64+i(+64 if q)] * aW[r][pq*64+i]
__global__ void prep_pq_kernel(const float* __restrict__ wW,
                               const float* __restrict__ wb,
                               const float* __restrict__ aW) {
    int idx = blockIdx.x * blockDim.x + threadIdx.x;
    if (idx < 24 * IN_F) {
        int k = idx & (IN_F - 1);
        int v = idx >> 7;
        int r = v >> 3, rem = v & 7, head = rem >> 1, pq = rem & 1;
        const float* wcol = wW + (size_t)r * IN_F * HH + (size_t)k * HH + head * HF;
        const float* av   = aW + r * 2 * HF + pq * HF;
        float s = 0.f;
        #pragma unroll 8
        for (int i = 0; i < HF; i++) s += wcol[i] * av[i];
        g_wpa[idx] = s;
    }
    if (idx < 24) {
        int r = idx >> 3, rem = idx & 7, head = rem >> 1, pq = rem & 1;
        const float* bb = wb + r * HH + head * HF;
        const float* av = aW + r * 2 * HF + pq * HF;
        float s = 0.f;
        for (int i = 0; i < HF; i++) s += bb[i] * av[i];
        g_pqc[idx] = s;
    }
}

// ---------------- per-node: sign scalars + 24 p/q projections --------------
__global__ void node_kernel(const float* __restrict__ h) {
    int warp = (blockIdx.x * blockDim.x + threadIdx.x) >> 5;
    int lane = threadIdx.x & 31;
    if (warp >= NN) return;
    float4 hv = *(const float4*)(h + (size_t)warp * IN_F + lane * 4);
    float4 us = *(const float4*)(g_us + lane * 4);
    float4 ud = *(const float4*)(g_ud + lane * 4);
    float ps = dot4(hv, us), pd = dot4(hv, ud);
    #pragma unroll
    for (int o = 16; o; o >>= 1) {
        ps += __shfl_xor_sync(0xffffffffu, ps, o);
        pd += __shfl_xor_sync(0xffffffffu, pd, o);
    }
    float myval = 0.f;
    #pragma unroll
    for (int v = 0; v < 24; v++) {
        float4 wv = *(const float4*)(g_wpa + v * IN_F + lane * 4);
        float s = dot4(hv, wv);
        #pragma unroll
        for (int o = 16; o; o >>= 1) s += __shfl_xor_sync(0xffffffffu, s, o);
        if (lane == v) myval = s;
    }
    if (lane == 0) { g_as[warp] = ps + g_c[0]; g_ad[warp] = pd + g_c[1]; }
    if (lane < 24) {
        int r = lane >> 3, rem = lane & 7, head = rem >> 1, pq = rem & 1;
        float o = myval + g_pqc[lane];
        int off = (warp * RR + r) * AHD + head;
        if (pq == 0) g_p[off] = o; else g_q[off] = o;
    }
}

// ---------------- fused edge phase: sign, alpha, exp, denom ----------------
// alpha is O(1) here, so softmax without max-subtraction is exact and safe.
__global__ void edge_kernel(const int* __restrict__ src, const int* __restrict__ dst,
                            const float* __restrict__ ab) {
    int idx = blockIdx.x * blockDim.x + threadIdx.x;
    if (idx >= RR * EE) return;
    int r = idx / EE;
    int s = src[idx], d = dst[idx];
    float sc = g_as[s] + g_ad[d];
    float sg = (sc > 0.f) ? 1.f : ((sc < 0.f) ? -1.f : 0.f);
    float4 pv = *(const float4*)(g_p + (s*RR + r)*AHD);
    float4 qv = *(const float4*)(g_q + (d*RR + r)*AHD);
    float abr = ab[r];
    float4 e;
    e.x = expf(lrelu(sg*pv.x + qv.x + abr));
    e.y = expf(lrelu(sg*pv.y + qv.y + abr));
    e.z = expf(lrelu(sg*pv.z + qv.z + abr));
    e.w = expf(lrelu(sg*pv.w + qv.w + abr));
    float* dn = g_den + (d*RR + r)*AHD;
    atomicAdd(dn+0, e.x);
    atomicAdd(dn+1, e.y);
    atomicAdd(dn+2, e.z);
    atomicAdd(dn+3, e.w);
    float4 es = make_float4(sg*e.x, sg*e.y, sg*e.z, sg*e.w);
    *(float4*)(g_ex + (size_t)idx * AHD) = es;
}

// ---------------- edge phase 2: weighted message scatter (heavy) -----------
__global__ void aggregate_kernel(const int* __restrict__ src, const int* __restrict__ dst) {
    int gw   = (blockIdx.x * blockDim.x + threadIdx.x) >> 5;
    int lane = threadIdx.x & 31;
    if (gw >= RR * EE) return;
    int r = gw / EE;
    int s = src[gw], d = dst[gw];
    int head = lane >> 3;
    float coef = g_ex[(size_t)gw * AHD + head] / g_den[(d*RR + r)*AHD + head];
    const float4* hs = (const float4*)(g_hw   + (size_t)s * RH + r * HH) + lane * 2;
    float4*       od = (float4*)      (g_oacc + (size_t)d * RH + r * HH) + lane * 2;
    float4 v0 = hs[0], v1 = hs[1];
    atomicAdd(od,     make_float4(coef*v0.x, coef*v0.y, coef*v0.z, coef*v0.w));
    atomicAdd(od + 1, make_float4(coef*v1.x, coef*v1.y, coef*v1.z, coef*v1.w));
}

// ---------------- launch ---------------------------------------------------
extern "C" void kernel_launch(void* const* d_in, const int* in_sizes, int n_in,
                              void* d_out, int out_size) {
    const float* h    = (const float*)d_in[0];
    const float* dW   = (const float*)d_in[1];
    const float* db   = (const float*)d_in[2];
    const float* fW   = (const float*)d_in[3];
    const float* fb   = (const float*)d_in[4];
    const float* wW   = (const float*)d_in[5];
    const float* wb   = (const float*)d_in[6];
    const float* aW   = (const float*)d_in[7];
    const float* ab   = (const float*)d_in[8];
    const float* linW = (const float*)d_in[9];
    const float* linb = (const float*)d_in[10];
    const int*   src  = (const int*)d_in[11];
    const int*   dst  = (const int*)d_in[12];
    float* out = (float*)d_out;

    float *hw, *oacc, *den, *wWt, *linWt;
    cudaGetSymbolAddress((void**)&hw,    g_hw);
    cudaGetSymbolAddress((void**)&oacc,  g_oacc);
    cudaGetSymbolAddress((void**)&den,   g_den);
    cudaGetSymbolAddress((void**)&wWt,   g_wWt);
    cudaGetSymbolAddress((void**)&linWt, g_linWt);

    cudaMemsetAsync(oacc, 0, (size_t)NN * RH * sizeof(float), 0);
    cudaMemsetAsync(den,  0, (size_t)NN * RR * AHD * sizeof(float), 0);

    transpose_weights_kernel<<<(HH * RH + 255) / 256, 256>>>(wW, linW);
    prep_kernel<<<1, 128>>>(dW, db, fW, fb);
    prep_pq_kernel<<<(24 * IN_F + 255) / 256, 256>>>(wW, wb, aW);
    node_kernel<<<(NN + 7) / 8, 256>>>(h);

    int mtiles = (NN + 127) / 128;
    // hw[r] = h @ wW[r] + wb[r], all 3 relations in one launch (z)
    mma_gemm_kernel<<<dim3(2, mtiles, RR), 256>>>(
        h, IN_F,
        wWt, IN_F, HH * IN_F,
        wb, HH,
        hw, RH, HH,
        NN, IN_F);

    edge_kernel<<<(RR * EE + 255) / 256, 256>>>(src, dst, ab);
    aggregate_kernel<<<(RR * EE + 7) / 8, 256>>>(src, dst);

    // out = oacc @ linW + linb
    mma_gemm_kernel<<<dim3(2, mtiles, 1), 256>>>(
        oacc, RH,
        linWt, RH, 0,
        linb, 0,
        out, HH, 0,
        NN, RH);
}

// round 4
// speedup vs baseline: 1.6296x; 1.5689x over previous
#include <cuda_runtime.h>
#include <cuda_bf16.h>
#include <math.h>
#include <cstdint>

#define NN   50000
#define EE   300000
#define IN_F 128
#define HH   256      // H = HF*AH
#define RR   3
#define AHD  4
#define HF   64
#define RH   (RR*HH)  // 768
#define NR   (NN*RR)  // 150000 segments

// ---------------- scratch (device globals; no allocation allowed) ----------
__device__ float g_hw[(size_t)NN*RH];     // h @ wW[r] for all r   (153.6MB)
__device__ float g_oacc[(size_t)NN*RH];   // aggregated messages   (153.6MB)
__device__ float g_as[NN];
__device__ float g_ad[NN];
__device__ float g_p[NN*RR*AHD];
__device__ float g_q[NN*RR*AHD];
__device__ float g_ex[(size_t)RR*EE*AHD]; // exp(alpha) (unsigned)
__device__ float g_sgn[RR*EE];            // per-edge sign
__device__ float g_wall[28*IN_F];         // 24 folded p/q dirs + us + ud (+2 pad rows, zero)
__device__ float g_wallc[28];             // constants per projection
__device__ float g_wWt[RR*HH*IN_F];       // wW transposed -> [r][n=256][k=128]
__device__ float g_linWt[HH*RH];          // linW transposed -> [n=256][k=768]
// CSR scratch
__device__ int   g_cnt[NR];
__device__ int   g_off[NR+1];
__device__ int   g_pos[NR];
__device__ int   g_elist[RR*EE];

// ---------------- helpers --------------------------------------------------
__device__ __forceinline__ float lrelu(float x) { return x > 0.f ? x : 0.01f * x; }

// ================= bf16 split mma.sync GEMM ================================
__device__ __forceinline__ void mma16816(float* c, const uint32_t* a, uint32_t b0, uint32_t b1) {
    asm volatile(
        "mma.sync.aligned.m16n8k16.row.col.f32.bf16.bf16.f32 "
        "{%0,%1,%2,%3}, {%4,%5,%6,%7}, {%8,%9}, {%0,%1,%2,%3};"
        : "+f"(c[0]), "+f"(c[1]), "+f"(c[2]), "+f"(c[3])
        : "r"(a[0]), "r"(a[1]), "r"(a[2]), "r"(a[3]), "r"(b0), "r"(b1));
}

__device__ __forceinline__ void cvt_store(char* hi_base, char* lo_base, int soff, float4 v) {
    __nv_bfloat162 h01 = __floats2bfloat162_rn(v.x, v.y);
    __nv_bfloat162 h23 = __floats2bfloat162_rn(v.z, v.w);
    float lx = v.x - __low2float(h01),  ly = v.y - __high2float(h01);
    float lz = v.z - __low2float(h23),  lw = v.w - __high2float(h23);
    __nv_bfloat162 l01 = __floats2bfloat162_rn(lx, ly);
    __nv_bfloat162 l23 = __floats2bfloat162_rn(lz, lw);
    uint2 hu, lu;
    hu.x = *(uint32_t*)&h01; hu.y = *(uint32_t*)&h23;
    lu.x = *(uint32_t*)&l01; lu.y = *(uint32_t*)&l23;
    *(uint2*)(hi_base + soff) = hu;
    *(uint2*)(lo_base + soff) = lu;
}

__global__ void __launch_bounds__(256) mma_gemm_kernel(
    const float* __restrict__ A, int lda,
    const float* __restrict__ Bt0, int ldb, int b_stride,
    const float* __restrict__ bias0, int bias_stride,
    float* __restrict__ C0, int ldc, int c_stride,
    int M, int K)
{
    __shared__ __align__(16) char sAh[8192];
    __shared__ __align__(16) char sAl[8192];
    __shared__ __align__(16) char sBh[8192];
    __shared__ __align__(16) char sBl[8192];

    const float* Bt   = Bt0   + (size_t)blockIdx.z * b_stride;
    const float* bias = bias0 + (size_t)blockIdx.z * bias_stride;
    float*       C    = C0    + (size_t)blockIdx.z * c_stride;

    int tid = threadIdx.x;
    int wid = tid >> 5, lane = tid & 31;
    int g = lane >> 2, tig = lane & 3;
    int wm = wid & 3, wn = wid >> 2;
    int bm = blockIdx.y * 128, bn = blockIdx.x * 128;

    float c[2][8][4];
    #pragma unroll
    for (int t = 0; t < 2; t++)
        #pragma unroll
        for (int nt = 0; nt < 8; nt++)
            #pragma unroll
            for (int i = 0; i < 4; i++) c[t][nt][i] = 0.f;

    int nch = K >> 5;
    float4 areg[4], breg[4];
    int rrow[4], rkq[4];

    #pragma unroll
    for (int i = 0; i < 4; i++) {
        int lin = i * 256 + tid;
        int row = lin >> 3, kq = (lin & 7) << 2;
        rrow[i] = row; rkq[i] = kq;
        int gr = bm + row;
        areg[i] = (gr < M) ? *(const float4*)(A + (size_t)gr * lda + kq)
                           : make_float4(0.f, 0.f, 0.f, 0.f);
        breg[i] = *(const float4*)(Bt + (size_t)(bn + row) * ldb + kq);
    }
    #pragma unroll
    for (int i = 0; i < 4; i++) {
        int soff = rrow[i] * 64 + ((rkq[i] << 1) ^ ((rrow[i] & 7) << 3));
        cvt_store(sAh, sAl, soff, areg[i]);
        cvt_store(sBh, sBl, soff, breg[i]);
    }
    __syncthreads();

    for (int ch = 0; ch < nch; ch++) {
        bool more = (ch + 1) < nch;
        if (more) {
            int kc = (ch + 1) << 5;
            #pragma unroll
            for (int i = 0; i < 4; i++) {
                int gr = bm + rrow[i];
                areg[i] = (gr < M) ? *(const float4*)(A + (size_t)gr * lda + kc + rkq[i])
                                   : make_float4(0.f, 0.f, 0.f, 0.f);
                breg[i] = *(const float4*)(Bt + (size_t)(bn + rrow[i]) * ldb + kc + rkq[i]);
            }
        }
        #pragma unroll
        for (int ks = 0; ks < 2; ks++) {
            uint32_t ah[2][4], al[2][4];
            int kb = ks * 32 + tig * 4;
            #pragma unroll
            for (int t = 0; t < 2; t++) {
                int r = wm * 32 + t * 16 + g;
                int x = (r & 7) << 3;
                int o0 = r * 64 + (kb ^ x);
                int o2 = r * 64 + ((kb + 16) ^ x);
                ah[t][0] = *(uint32_t*)(sAh + o0);
                ah[t][1] = *(uint32_t*)(sAh + o0 + 512);
                ah[t][2] = *(uint32_t*)(sAh + o2);
                ah[t][3] = *(uint32_t*)(sAh + o2 + 512);
                al[t][0] = *(uint32_t*)(sAl + o0);
                al[t][1] = *(uint32_t*)(sAl + o0 + 512);
                al[t][2] = *(uint32_t*)(sAl + o2);
                al[t][3] = *(uint32_t*)(sAl + o2 + 512);
            }
            #pragma unroll
            for (int nt = 0; nt < 8; nt++) {
                int n = wn * 64 + nt * 8 + g;
                int x = (n & 7) << 3;
                int o0 = n * 64 + (kb ^ x);
                int o1 = n * 64 + ((kb + 16) ^ x);
                uint32_t bh0 = *(uint32_t*)(sBh + o0);
                uint32_t bh1 = *(uint32_t*)(sBh + o1);
                uint32_t bl0 = *(uint32_t*)(sBl + o0);
                uint32_t bl1 = *(uint32_t*)(sBl + o1);
                #pragma unroll
                for (int t = 0; t < 2; t++) {
                    mma16816(c[t][nt], ah[t], bh0, bh1);
                    mma16816(c[t][nt], ah[t], bl0, bl1);
                    mma16816(c[t][nt], al[t], bh0, bh1);
                }
            }
        }
        if (more) {
            __syncthreads();
            #pragma unroll
            for (int i = 0; i < 4; i++) {
                int soff = rrow[i] * 64 + ((rkq[i] << 1) ^ ((rrow[i] & 7) << 3));
                cvt_store(sAh, sAl, soff, areg[i]);
                cvt_store(sBh, sBl, soff, breg[i]);
            }
            __syncthreads();
        }
    }

    #pragma unroll
    for (int t = 0; t < 2; t++) {
        int row0 = bm + wm * 32 + t * 16 + g;
        #pragma unroll
        for (int nt = 0; nt < 8; nt++) {
            int col = bn + wn * 64 + nt * 8 + tig * 2;
            float b0 = bias[col], b1 = bias[col + 1];
            if (row0 < M) {
                float2 o = make_float2(c[t][nt][0] + b0, c[t][nt][1] + b1);
                *(float2*)(C + (size_t)row0 * ldc + col) = o;
            }
            if (row0 + 8 < M) {
                float2 o = make_float2(c[t][nt][2] + b0, c[t][nt][3] + b1);
                *(float2*)(C + (size_t)(row0 + 8) * ldc + col) = o;
            }
        }
    }
}

// ---------------- weight transposes ----------------------------------------
__global__ void transpose_weights_kernel(const float* __restrict__ wW,
                                         const float* __restrict__ linW) {
    int idx = blockIdx.x * blockDim.x + threadIdx.x;
    if (idx < RR * HH * IN_F) {
        int r = idx / (HH * IN_F);
        int rem = idx - r * HH * IN_F;
        int n = rem / IN_F, k = rem - n * IN_F;
        g_wWt[idx] = wW[(size_t)r * IN_F * HH + (size_t)k * HH + n];
    }
    if (idx < HH * RH) {
        int n = idx / RH, k = idx - n * RH;
        g_linWt[idx] = linW[(size_t)k * HH + n];
    }
}

// ---------------- prep: fold d_liner+f_liner -> wall rows 24/25 ------------
__global__ void prep_kernel(const float* __restrict__ dW, const float* __restrict__ db,
                            const float* __restrict__ fW, const float* __restrict__ fb) {
    int k = threadIdx.x;
    if (k < IN_F) {
        float us = 0.f, ud = 0.f;
        for (int j = 0; j < HH; j++) {
            float w  = dW[k*HH + j];
            float f0 = fW[j], f1 = fW[HH + j], f2 = fW[2*HH + j];
            us += w * (f0 + f2);
            ud += w * (f1 - f2);
        }
        g_wall[24*IN_F + k] = us;
        g_wall[25*IN_F + k] = ud;
    }
    if (k == 0) {
        float cs = 0.f, cd = 0.f;
        for (int j = 0; j < HH; j++) {
            float b  = db[j];
            float f0 = fW[j], f1 = fW[HH + j], f2 = fW[2*HH + j];
            cs += b * (f0 + f2);
            cd += b * (f1 - f2);
        }
        g_wallc[24] = cs + fb[0];
        g_wallc[25] = cd;
    }
}

// ---------------- fold w_liner+attention into wall rows 0..23 --------------
__global__ void prep_pq_kernel(const float* __restrict__ wW,
                               const float* __restrict__ wb,
                               const float* __restrict__ aW) {
    int idx = blockIdx.x * blockDim.x + threadIdx.x;
    if (idx < 24 * IN_F) {
        int k = idx & (IN_F - 1);
        int v = idx >> 7;
        int r = v >> 3, rem = v & 7, head = rem >> 1, pq = rem & 1;
        const float* wcol = wW + (size_t)r * IN_F * HH + (size_t)k * HH + head * HF + pq * (AHD * HF);
        // note: q uses columns head*HF within hw[d] second half? No: q = hw[d] row, cols head*64..;
        // p uses aW first half against sf (src), q uses aW second half against dst features.
        // Both p and q project the SAME hw columns head*64..head*64+63, just different aW halves.
        wcol = wW + (size_t)r * IN_F * HH + (size_t)k * HH + head * HF;
        const float* av = aW + r * 2 * HF + pq * HF;
        float s = 0.f;
        #pragma unroll 8
        for (int i = 0; i < HF; i++) s += wcol[i] * av[i];
        g_wall[idx] = s;
    }
    if (idx < 24) {
        int r = idx >> 3, rem = idx & 7, head = rem >> 1, pq = rem & 1;
        const float* bb = wb + r * HH + head * HF;
        const float* av = aW + r * 2 * HF + pq * HF;
        float s = 0.f;
        for (int i = 0; i < HF; i++) s += bb[i] * av[i];
        g_wallc[idx] = s;
    }
}

// ---------------- per-node projections: smem-tiled, no shuffles ------------
// 128 threads, 64 nodes/block, thread = (nrow 0..31, sub 0..3), 2 nodes/thread,
// 7 projections/thread (28 slots, rows 26/27 are zero padding).
__global__ void __launch_bounds__(128) node_kernel(const float* __restrict__ h) {
    __shared__ float sh[64][132];
    __shared__ float sw[28][132];
    __shared__ float sc[28];
    int t = threadIdx.x;
    int nb = blockIdx.x * 64;

    #pragma unroll
    for (int i = 0; i < 16; i++) {          // 2048 float4 h tile
        int lin = i * 128 + t;
        int row = lin >> 5, kq = (lin & 31) << 2;
        int gn = nb + row;
        float4 v = make_float4(0.f, 0.f, 0.f, 0.f);
        if (gn < NN) v = *(const float4*)(h + (size_t)gn * IN_F + kq);
        *(float4*)&sh[row][kq] = v;
    }
    #pragma unroll
    for (int i = 0; i < 7; i++) {           // 896 slots >= 28*32 float4
        int lin = i * 128 + t;
        if (lin < 28 * 32) {
            int row = lin >> 5, kq = (lin & 31) << 2;
            *(float4*)&sw[row][kq] = *(const float4*)(g_wall + row * IN_F + kq);
        }
    }
    if (t < 28) sc[t] = g_wallc[t];
    __syncthreads();

    int nrow = t >> 2, sub = t & 3;
    float acc0[7], acc1[7];
    #pragma unroll
    for (int j = 0; j < 7; j++) { acc0[j] = 0.f; acc1[j] = 0.f; }
    for (int k = 0; k < IN_F; k++) {
        float h0 = sh[nrow][k];
        float h1 = sh[nrow + 32][k];
        #pragma unroll
        for (int j = 0; j < 7; j++) {
            float w = sw[sub * 7 + j][k];
            acc0[j] = fmaf(h0, w, acc0[j]);
            acc1[j] = fmaf(h1, w, acc1[j]);
        }
    }
    #pragma unroll
    for (int m = 0; m < 2; m++) {
        int gn = nb + nrow + 32 * m;
        if (gn >= NN) continue;
        #pragma unroll
        for (int j = 0; j < 7; j++) {
            int v = sub * 7 + j;
            if (v >= 26) continue;
            float val = (m ? acc1[j] : acc0[j]) + sc[v];
            if (v < 24) {
                int r = v >> 3, rem = v & 7, head = rem >> 1, pq = rem & 1;
                int off = (gn * RR + r) * AHD + head;
                if (pq == 0) g_p[off] = val; else g_q[off] = val;
            } else if (v == 24) g_as[gn] = val;
            else                g_ad[gn] = val;
        }
    }
}

// ---------------- CSR build ------------------------------------------------
__global__ void count_kernel(const int* __restrict__ dst) {
    int idx = blockIdx.x * blockDim.x + threadIdx.x;
    if (idx >= RR * EE) return;
    int r = idx / EE;
    atomicAdd(&g_cnt[r * NN + dst[idx]], 1);
}

// single block, 1024 threads, exclusive scan over NR counts
__global__ void __launch_bounds__(1024) scan_kernel() {
    __shared__ int ssum[1024];
    int t = threadIdx.x;
    const int PER = (NR + 1023) / 1024;
    int base = t * PER;
    int s = 0;
    for (int i = 0; i < PER; i++) {
        int idx = base + i;
        if (idx < NR) s += g_cnt[idx];
    }
    ssum[t] = s;
    __syncthreads();
    for (int o = 1; o < 1024; o <<= 1) {
        int w = 0;
        if (t >= o) w = ssum[t - o];
        __syncthreads();
        ssum[t] += w;
        __syncthreads();
    }
    int run = ssum[t] - s;  // exclusive prefix
    for (int i = 0; i < PER; i++) {
        int idx = base + i;
        if (idx < NR) { g_off[idx] = run; run += g_cnt[idx]; }
    }
    if (t == 1023) g_off[NR] = run;
}

__global__ void scatter_kernel(const int* __restrict__ dst) {
    int idx = blockIdx.x * blockDim.x + threadIdx.x;
    if (idx >= RR * EE) return;
    int r = idx / EE;
    int seg = r * NN + dst[idx];
    int p = atomicAdd(&g_pos[seg], 1);
    g_elist[g_off[seg] + p] = idx;
}

// ---------------- edge phase: sign, alpha, exp (no atomics) ----------------
__global__ void edge_kernel(const int* __restrict__ src, const int* __restrict__ dst,
                            const float* __restrict__ ab) {
    int idx = blockIdx.x * blockDim.x + threadIdx.x;
    if (idx >= RR * EE) return;
    int r = idx / EE;
    int s = src[idx], d = dst[idx];
    float sc = g_as[s] + g_ad[d];
    float sg = (sc > 0.f) ? 1.f : ((sc < 0.f) ? -1.f : 0.f);
    float4 pv = *(const float4*)(g_p + (s*RR + r)*AHD);
    float4 qv = *(const float4*)(g_q + (d*RR + r)*AHD);
    float abr = ab[r];
    float4 e;
    e.x = expf(lrelu(sg*pv.x + qv.x + abr));
    e.y = expf(lrelu(sg*pv.y + qv.y + abr));
    e.z = expf(lrelu(sg*pv.z + qv.z + abr));
    e.w = expf(lrelu(sg*pv.w + qv.w + abr));
    *(float4*)(g_ex + (size_t)idx * AHD) = e;
    g_sgn[idx] = sg;
}

// ---------------- CSR aggregate: warp per (r,dst), no atomics --------------
__global__ void aggregate_csr_kernel(const int* __restrict__ src) {
    int gw   = (blockIdx.x * blockDim.x + threadIdx.x) >> 5;
    int lane = threadIdx.x & 31;
    if (gw >= NR) return;
    int r = gw / NN, d = gw - r * NN;
    int beg = g_off[gw], end = g_off[gw + 1];
    float* orow = g_oacc + (size_t)d * RH + r * HH + lane * 8;

    if (beg == end) {
        float4 z = make_float4(0.f, 0.f, 0.f, 0.f);
        *(float4*)orow = z;
        *(float4*)(orow + 4) = z;
        return;
    }

    // denominator: sum exp over incident edges (4 heads)
    float dx = 0.f, dy = 0.f, dz = 0.f, dw = 0.f;
    for (int j = beg + lane; j < end; j += 32) {
        int idx = g_elist[j];
        float4 e = *(const float4*)(g_ex + (size_t)idx * AHD);
        dx += e.x; dy += e.y; dz += e.z; dw += e.w;
    }
    #pragma unroll
    for (int o = 16; o; o >>= 1) {
        dx += __shfl_xor_sync(0xffffffffu, dx, o);
        dy += __shfl_xor_sync(0xffffffffu, dy, o);
        dz += __shfl_xor_sync(0xffffffffu, dz, o);
        dw += __shfl_xor_sync(0xffffffffu, dw, o);
    }
    int head = lane >> 3;
    float den = (head == 0) ? dx : (head == 1) ? dy : (head == 2) ? dz : dw;
    float deninv = 1.f / den;

    float a0=0.f,a1=0.f,a2=0.f,a3=0.f,a4=0.f,a5=0.f,a6=0.f,a7=0.f;
    for (int j = beg; j < end; j++) {
        int idx = g_elist[j];
        float ex = g_ex[(size_t)idx * AHD + head];
        float sg = g_sgn[idx];
        int s = src[idx];
        const float4* hr = (const float4*)(g_hw + (size_t)s * RH + r * HH) + lane * 2;
        float4 v0 = hr[0], v1 = hr[1];
        float cf = ex * deninv * sg;
        a0 = fmaf(cf, v0.x, a0); a1 = fmaf(cf, v0.y, a1);
        a2 = fmaf(cf, v0.z, a2); a3 = fmaf(cf, v0.w, a3);
        a4 = fmaf(cf, v1.x, a4); a5 = fmaf(cf, v1.y, a5);
        a6 = fmaf(cf, v1.z, a6); a7 = fmaf(cf, v1.w, a7);
    }
    *(float4*)orow       = make_float4(a0, a1, a2, a3);
    *(float4*)(orow + 4) = make_float4(a4, a5, a6, a7);
}

// ---------------- launch ---------------------------------------------------
extern "C" void kernel_launch(void* const* d_in, const int* in_sizes, int n_in,
                              void* d_out, int out_size) {
    const float* h    = (const float*)d_in[0];
    const float* dW   = (const float*)d_in[1];
    const float* db   = (const float*)d_in[2];
    const float* fW   = (const float*)d_in[3];
    const float* fb   = (const float*)d_in[4];
    const float* wW   = (const float*)d_in[5];
    const float* wb   = (const float*)d_in[6];
    const float* aW   = (const float*)d_in[7];
    const float* ab   = (const float*)d_in[8];
    const float* linW = (const float*)d_in[9];
    const float* linb = (const float*)d_in[10];
    const int*   src  = (const int*)d_in[11];
    const int*   dst  = (const int*)d_in[12];
    float* out = (float*)d_out;

    float *hw, *oacc, *wWt, *linWt;
    int *cnt, *pos;
    cudaGetSymbolAddress((void**)&hw,    g_hw);
    cudaGetSymbolAddress((void**)&oacc,  g_oacc);
    cudaGetSymbolAddress((void**)&wWt,   g_wWt);
    cudaGetSymbolAddress((void**)&linWt, g_linWt);
    cudaGetSymbolAddress((void**)&cnt,   g_cnt);
    cudaGetSymbolAddress((void**)&pos,   g_pos);

    cudaMemsetAsync(cnt, 0, NR * sizeof(int), 0);
    cudaMemsetAsync(pos, 0, NR * sizeof(int), 0);

    transpose_weights_kernel<<<(HH * RH + 255) / 256, 256>>>(wW, linW);
    prep_kernel<<<1, 128>>>(dW, db, fW, fb);
    prep_pq_kernel<<<(24 * IN_F + 255) / 256, 256>>>(wW, wb, aW);
    node_kernel<<<(NN + 63) / 64, 128>>>(h);

    // CSR build (depends only on dst)
    count_kernel<<<(RR * EE + 255) / 256, 256>>>(dst);
    scan_kernel<<<1, 1024>>>();
    scatter_kernel<<<(RR * EE + 255) / 256, 256>>>(dst);

    int mtiles = (NN + 127) / 128;
    mma_gemm_kernel<<<dim3(2, mtiles, RR), 256>>>(
        h, IN_F,
        wWt, IN_F, HH * IN_F,
        wb, HH,
        hw, RH, HH,
        NN, IN_F);

    edge_kernel<<<(RR * EE + 255) / 256, 256>>>(src, dst, ab);
    aggregate_csr_kernel<<<(NR + 7) / 8, 256>>>(src);

    mma_gemm_kernel<<<dim3(2, mtiles, 1), 256>>>(
        oacc, RH,
        linWt, RH, 0,
        linb, 0,
        out, HH, 0,
        NN, RH);
}